// round 1
// baseline (speedup 1.0000x reference)
#include <cuda_runtime.h>
#include <cuda_bf16.h>

// Blur_82471962018173: depthwise separable 4x4 FIR ([1,3,3,1]/4 per axis),
// input (4,128,513,513) f32, pad=1 both sides, output (4,128,512,512) f32.
// Kernel is symmetric -> flip is identity. Weights hardcoded (deterministic).
//
// Each thread: 4-wide x 16-tall output strip. Horizontal 4-tap from 7 scalar
// loads per row, vertical 4-tap via rolling register window. float4 stores.

#define ROWS_PER_THREAD 16
#define W_IN  513
#define W_OUT 512

__global__ __launch_bounds__(128)
void blur_kernel(const float* __restrict__ in, float* __restrict__ out) {
    const int nc = blockIdx.z;                 // 0..511 (N*C)
    const int y0 = blockIdx.y * ROWS_PER_THREAD;
    const int x0 = threadIdx.x << 2;           // 0,4,...,508

    const float* __restrict__ inp  = in  + (size_t)nc * (W_IN  * W_IN);
    float*       __restrict__ outp = out + (size_t)nc * (W_OUT * W_OUT);

    const bool left  = (x0 == 0);     // x0-1 would be -1
    const bool right = (x0 >= 508);   // x0+5 would be 513 (max valid 512)

    float4 h[4];                       // rolling horizontal-filtered rows

    #pragma unroll
    for (int r = 0; r < ROWS_PER_THREAD + 3; ++r) {
        const int yy = y0 - 1 + r;     // input row index
        float v0, v1, v2, v3, v4, v5, v6;
        if (yy >= 0 && yy < W_IN) {
            const float* rp = inp + (size_t)yy * W_IN + x0;
            v0 = left  ? 0.f : rp[-1];
            v1 = rp[0]; v2 = rp[1]; v3 = rp[2]; v4 = rp[3]; v5 = rp[4];
            v6 = right ? 0.f : rp[5];
        } else {
            v0 = v1 = v2 = v3 = v4 = v5 = v6 = 0.f;
        }
        // horizontal 4-tap, weights {0.25, 0.75, 0.75, 0.25}
        float4 hc;
        hc.x = 0.25f * (v0 + v3) + 0.75f * (v1 + v2);
        hc.y = 0.25f * (v1 + v4) + 0.75f * (v2 + v3);
        hc.z = 0.25f * (v2 + v5) + 0.75f * (v3 + v4);
        hc.w = 0.25f * (v3 + v6) + 0.75f * (v4 + v5);
        h[r & 3] = hc;

        if (r >= 3) {
            const int yo = y0 + r - 3;   // output row, always in [0,511]
            const float4 a = h[(r - 3) & 3];
            const float4 b = h[(r - 2) & 3];
            const float4 c = h[(r - 1) & 3];
            const float4 d = hc;
            float4 o;
            o.x = 0.25f * (a.x + d.x) + 0.75f * (b.x + c.x);
            o.y = 0.25f * (a.y + d.y) + 0.75f * (b.y + c.y);
            o.z = 0.25f * (a.z + d.z) + 0.75f * (b.z + c.z);
            o.w = 0.25f * (a.w + d.w) + 0.75f * (b.w + c.w);
            *reinterpret_cast<float4*>(outp + (size_t)yo * W_OUT + x0) = o;
        }
    }
}

extern "C" void kernel_launch(void* const* d_in, const int* in_sizes, int n_in,
                              void* d_out, int out_size) {
    const float* in = (const float*)d_in[0];   // (4,128,513,513) f32
    float* out = (float*)d_out;                // (4,128,512,512) f32
    // grid: x covers full 512-wide row with 128 threads * 4 cols,
    //       y = 512/16 row-strips, z = N*C = 512
    dim3 grid(1, W_OUT / ROWS_PER_THREAD, 4 * 128);
    blur_kernel<<<grid, 128>>>(in, out);
}

// round 2
// speedup vs baseline: 1.0139x; 1.0139x over previous
#include <cuda_runtime.h>
#include <cuda_bf16.h>

// Blur_82471962018173: depthwise separable 4x4 FIR ([1,3,3,1]/4 per axis),
// input (4,128,513,513) f32, pad=1 both sides, output (4,128,512,512) f32.
//
// R2: smem row staging. Cooperative stride-1 global loads (1 L1 wavefront per
// warp LDG), horizontal window read back as two conflict-free LDS.128,
// vertical 4-tap rolled in registers. Double-buffered rows -> 1 bar/row.

#define W_IN  513
#define W_OUT 512
#define ROWS  32          // output rows per block
#define NT    128

__global__ __launch_bounds__(NT)
void blur_kernel(const float* __restrict__ in, float* __restrict__ out) {
    __shared__ float sbuf[2][520];   // s[i] holds input x = i-1 (zero-padded)

    const int nc = blockIdx.z;                 // N*C plane
    const int y0 = blockIdx.y * ROWS;
    const int t  = threadIdx.x;
    const int x0 = t << 2;                     // output cols x0..x0+3

    const float* __restrict__ inp  = in  + (size_t)nc * (W_IN  * W_IN);
    float*       __restrict__ outp = out + (size_t)nc * (W_OUT * W_OUT);

    float4 h[4];   // rolling horizontally-filtered rows

    auto load_row = [&](int r) {
        const int yy = y0 - 1 + r;
        float* s = sbuf[r & 1];
        const bool rowok = (yy >= 0) && (yy < W_IN);
        const float* rp = inp + (size_t)yy * W_IN;
        #pragma unroll
        for (int i = t; i < 515; i += NT) {    // i=0 -> x=-1 pad, i=514 -> x=513 pad
            const int x = i - 1;
            float v = 0.f;
            if (rowok && x >= 0 && x < W_IN) v = rp[x];
            s[i] = v;
        }
    };

    auto hfilt = [&](int r) {
        const float* s = sbuf[r & 1];
        const float4 A = *(const float4*)(s + x0);      // x0-1 .. x0+2
        const float4 B = *(const float4*)(s + x0 + 4);  // x0+3 .. x0+6
        float4 hc;
        hc.x = 0.25f * (A.x + A.w) + 0.75f * (A.y + A.z);
        hc.y = 0.25f * (A.y + B.x) + 0.75f * (A.z + A.w);
        hc.z = 0.25f * (A.z + B.y) + 0.75f * (A.w + B.x);
        hc.w = 0.25f * (A.w + B.z) + 0.75f * (B.x + B.y);
        h[r & 3] = hc;
    };

    // prologue: 3 rows fill the vertical window
    load_row(0); __syncthreads(); hfilt(0);
    load_row(1); __syncthreads(); hfilt(1);
    load_row(2); __syncthreads(); hfilt(2);

    #pragma unroll 4
    for (int k = 0; k < ROWS; ++k) {
        const int r = k + 3;
        load_row(r);
        __syncthreads();
        hfilt(r);

        const float4 a = h[(r - 3) & 3];
        const float4 b = h[(r - 2) & 3];
        const float4 c = h[(r - 1) & 3];
        const float4 d = h[r & 3];
        float4 o;
        o.x = 0.25f * (a.x + d.x) + 0.75f * (b.x + c.x);
        o.y = 0.25f * (a.y + d.y) + 0.75f * (b.y + c.y);
        o.z = 0.25f * (a.z + d.z) + 0.75f * (b.z + c.z);
        o.w = 0.25f * (a.w + d.w) + 0.75f * (b.w + c.w);
        *reinterpret_cast<float4*>(outp + (size_t)(y0 + k) * W_OUT + x0) = o;
    }
}

extern "C" void kernel_launch(void* const* d_in, const int* in_sizes, int n_in,
                              void* d_out, int out_size) {
    const float* in = (const float*)d_in[0];   // (4,128,513,513) f32
    float* out = (float*)d_out;                // (4,128,512,512) f32
    dim3 grid(1, W_OUT / ROWS, 4 * 128);       // 16 row-strips x 512 planes
    blur_kernel<<<grid, NT>>>(in, out);
}